// round 10
// baseline (speedup 1.0000x reference)
#include <cuda_runtime.h>
#include <cuda_bf16.h>
#include <cstdint>

#define B_SZ 8192
#define M_SZ 64
#define D_SZ 256
#define K2   1536   // Wc layout: [W_hi | W_lo | W_hi]

#define BM    32              // samples per CTA
#define LDX   1032            // sX row stride (bf16 elems), 16B-aligned rows
#define SX_E  (BM * LDX)      // 33024 elems
#define LDSK  72              // sB row stride (conflict-free for ldmatrix)
#define BSTG  (64 * LDSK)     // 4608 elems per B stage
#define BK    64
#define NKT   24              // k-tiles per n-chunk (virtual K = 1536)
#define NIT   96              // 4 n-chunks x 24
#define NSTG  4               // B pipeline stages

// weights in compensated bf16 (only remaining global scratch)
__device__ __align__(256) __nv_bfloat16 g_Wc[256 * K2];   // 768 KB

// ---------------------------------------------------------------------------
// helpers
// ---------------------------------------------------------------------------
__device__ __forceinline__ void cp_async16(void* smem_ptr, const void* gptr) {
    unsigned sa = (unsigned)__cvta_generic_to_shared(smem_ptr);
    asm volatile("cp.async.cg.shared.global [%0], [%1], 16;\n" :: "r"(sa), "l"(gptr));
}
__device__ __forceinline__ void cp_commit() {
    asm volatile("cp.async.commit_group;\n");
}
template<int N> __device__ __forceinline__ void cp_wait() {
    asm volatile("cp.async.wait_group %0;\n" :: "n"(N));
}
__device__ __forceinline__ void ldsm_x4(uint32_t r[4], const void* p) {
    unsigned a = (unsigned)__cvta_generic_to_shared(p);
    asm volatile("ldmatrix.sync.aligned.m8n8.x4.shared.b16 {%0,%1,%2,%3}, [%4];"
                 : "=r"(r[0]), "=r"(r[1]), "=r"(r[2]), "=r"(r[3]) : "r"(a));
}
__device__ __forceinline__ uint32_t packbf2(float x, float y) {
    __nv_bfloat162 t = __floats2bfloat162_rn(x, y);
    return *(uint32_t*)&t;
}
__device__ __forceinline__ uint32_t packbf2h(__nv_bfloat16 x, __nv_bfloat16 y) {
    __nv_bfloat162 t = __halves2bfloat162(x, y);
    return *(uint32_t*)&t;
}
__device__ __forceinline__ void mma16816(float c[4], const uint32_t a[4],
                                         const uint32_t b0, const uint32_t b1) {
    asm volatile(
        "mma.sync.aligned.m16n8k16.row.col.f32.bf16.bf16.f32 "
        "{%0,%1,%2,%3}, {%4,%5,%6,%7}, {%8,%9}, {%0,%1,%2,%3};\n"
        : "+f"(c[0]), "+f"(c[1]), "+f"(c[2]), "+f"(c[3])
        : "r"(a[0]), "r"(a[1]), "r"(a[2]), "r"(a[3]), "r"(b0), "r"(b1));
}

// virtual k-tile (BK=64, 24 tiles) -> X physical offset:
//  0..7: hi*Whi, 8..15: hi*Wlo, 16..23: lo*Whi
__device__ __forceinline__ int a_koff(int kt) {
    return (kt < 8) ? kt * BK : (kt < 16) ? (kt - 8) * BK
                                          : 512 + (kt - 16) * BK;
}

// ---------------------------------------------------------------------------
// W conversion: Wc[n] = [hi(W) | lo(W) | hi(W)], W[n] = [Wg_w[n] | Ug_w[n]]
// 2 elems/thread, bf16x2 stores. grid 768 x 256.
// ---------------------------------------------------------------------------
__global__ void conv_w_kernel(const float* __restrict__ Wg_w,
                              const float* __restrict__ Ug_w) {
    const int j0  = (blockIdx.x * 256 + threadIdx.x) * 2;
    const int n   = j0 / K2;
    const int jj  = j0 - n * K2;
    const int seg = jj >> 9;           // same for jj and jj+1 (even j0)
    __nv_bfloat16 v[2];
#pragma unroll
    for (int u = 0; u < 2; ++u) {
        const int k = (jj + u) & 511;
        const float w = (k < 256) ? Wg_w[n * 256 + k]
                                  : Ug_w[n * 256 + (k - 256)];
        const __nv_bfloat16 hi = __float2bfloat16_rn(w);
        v[u] = (seg == 1) ? __float2bfloat16_rn(w - __bfloat162float(hi)) : hi;
    }
    *(uint32_t*)(g_Wc + j0) = packbf2h(v[0], v[1]);
}

// ---------------------------------------------------------------------------
// FUSED kernel: phase 1 = warp-per-sample ragged attention (work stealing),
// X tile written to SMEM; phase 2 = bf16 MMA gate-GEMM on the SMEM X tile
// with W streamed through a 4-stage cp.async pipeline; fused epilogue.
// grid = 256 CTAs (one wave at 2 CTAs/SM), 256 threads.
// ---------------------------------------------------------------------------
struct Grp { float4 v[4][2]; };

__global__ __launch_bounds__(256, 2)
void fused_kernel(const float* __restrict__ h_tilde,
                  const float* __restrict__ mem,
                  const int* __restrict__ lengths,
                  const float* __restrict__ Wg_b,
                  const float* __restrict__ Ug_b,
                  const float* __restrict__ b_g,
                  float* __restrict__ out) {
    extern __shared__ __align__(16) __nv_bfloat16 smem[];
    __nv_bfloat16* sX = smem;            // BM x LDX
    __nv_bfloat16* sB = smem + SX_E;     // NSTG x BSTG
    __shared__ int s_cnt;

    const int tid   = threadIdx.x;
    const int warp  = tid >> 5;
    const int lane  = tid & 31;
    const int samp0 = blockIdx.x * BM;

    // B loader mapping
    const int lrB = tid >> 2;
    const int cB0 = (tid & 3) * 8;
    const int cB1 = cB0 + 32;

    if (tid == 0) s_cnt = 0;

    // prime first NSTG-1 W tiles (they ride out phase 1 in flight/in smem)
#pragma unroll
    for (int p = 0; p < NSTG - 1; ++p) {
        const __nv_bfloat16* gb =
            g_Wc + (size_t)((p / NKT) * 64 + lrB) * K2 + (p % NKT) * BK;
        cp_async16(sB + p * BSTG + lrB * LDSK + cB0, gb + cB0);
        cp_async16(sB + p * BSTG + lrB * LDSK + cB1, gb + cB1);
        cp_commit();
    }
    __syncthreads();   // s_cnt visible

    // ------------------ phase 1: attention (work-stealing) -----------------
    while (true) {
        int s;
        if (lane == 0) s = atomicAdd(&s_cnt, 1);
        s = __shfl_sync(0xffffffffu, s, 0);
        if (s >= BM) break;

        const int b   = samp0 + s;
        const int len = lengths[b];

        const float4* hp = (const float4*)(h_tilde + (size_t)b * D_SZ);
        const float4 ha = hp[lane * 2];
        const float4 hb = hp[lane * 2 + 1];

        float4 r0 = make_float4(0.f, 0.f, 0.f, 0.f);
        float4 r1 = make_float4(0.f, 0.f, 0.f, 0.f);

        if (len > 0) {
            const float4* base = (const float4*)(mem + (size_t)b * M_SZ * D_SZ);
            float Mrun = -3.0e38f, Srun = 0.f;
            Grp A, Bf;

            auto loadg = [&](Grp& R, int g) {
#pragma unroll
                for (int i = 0; i < 4; ++i) {
                    const int m = g * 4 + i;
                    R.v[i][0] = make_float4(0.f, 0.f, 0.f, 0.f);
                    R.v[i][1] = make_float4(0.f, 0.f, 0.f, 0.f);
                    if (m < len) {
                        const float4* rp = base + (size_t)m * 64 + lane * 2;
                        R.v[i][0] = rp[0];
                        R.v[i][1] = rp[1];
                    }
                }
            };
            auto process = [&](const Grp& R, int g) {
                float sc[4];
#pragma unroll
                for (int i = 0; i < 4; ++i) {
                    const float4 a = R.v[i][0];
                    const float4 c = R.v[i][1];
                    float acc = a.x * ha.x;
                    acc = fmaf(a.y, ha.y, acc);
                    acc = fmaf(a.z, ha.z, acc);
                    acc = fmaf(a.w, ha.w, acc);
                    acc = fmaf(c.x, hb.x, acc);
                    acc = fmaf(c.y, hb.y, acc);
                    acc = fmaf(c.z, hb.z, acc);
                    acc = fmaf(c.w, hb.w, acc);
#pragma unroll
                    for (int off = 16; off; off >>= 1)
                        acc += __shfl_xor_sync(0xffffffffu, acc, off);
                    sc[i] = (g * 4 + i < len) ? acc : -1e9f;
                }
                const float cmax = fmaxf(fmaxf(sc[0], sc[1]), fmaxf(sc[2], sc[3]));
                const float nM   = fmaxf(Mrun, cmax);
                const float corr = __expf(Mrun - nM);
                const float e0 = __expf(sc[0] - nM);
                const float e1 = __expf(sc[1] - nM);
                const float e2 = __expf(sc[2] - nM);
                const float e3 = __expf(sc[3] - nM);
                Srun = Srun * corr + (e0 + e1) + (e2 + e3);
                Mrun = nM;
                r0.x = fmaf(e0, R.v[0][0].x, fmaf(e1, R.v[1][0].x, fmaf(e2, R.v[2][0].x, fmaf(e3, R.v[3][0].x, r0.x * corr))));
                r0.y = fmaf(e0, R.v[0][0].y, fmaf(e1, R.v[1][0].y, fmaf(e2, R.v[2][0].y, fmaf(e3, R.v[3][0].y, r0.y * corr))));
                r0.z = fmaf(e0, R.v[0][0].z, fmaf(e1, R.v[1][0].z, fmaf(e2, R.v[2][0].z, fmaf(e3, R.v[3][0].z, r0.z * corr))));
                r0.w = fmaf(e0, R.v[0][0].w, fmaf(e1, R.v[1][0].w, fmaf(e2, R.v[2][0].w, fmaf(e3, R.v[3][0].w, r0.w * corr))));
                r1.x = fmaf(e0, R.v[0][1].x, fmaf(e1, R.v[1][1].x, fmaf(e2, R.v[2][1].x, fmaf(e3, R.v[3][1].x, r1.x * corr))));
                r1.y = fmaf(e0, R.v[0][1].y, fmaf(e1, R.v[1][1].y, fmaf(e2, R.v[2][1].y, fmaf(e3, R.v[3][1].y, r1.y * corr))));
                r1.z = fmaf(e0, R.v[0][1].z, fmaf(e1, R.v[1][1].z, fmaf(e2, R.v[2][1].z, fmaf(e3, R.v[3][1].z, r1.z * corr))));
                r1.w = fmaf(e0, R.v[0][1].w, fmaf(e1, R.v[1][1].w, fmaf(e2, R.v[2][1].w, fmaf(e3, R.v[3][1].w, r1.w * corr))));
            };

            const int ng = (len + 3) >> 2;
            loadg(A, 0);
            int g = 0;
            while (true) {
                if (g + 1 < ng) loadg(Bf, g + 1);
                process(A, g);
                ++g;
                if (g >= ng) break;
                if (g + 1 < ng) loadg(A, g + 1);
                process(Bf, g);
                ++g;
                if (g >= ng) break;
            }
            const float inv = 1.f / Srun;
            r0.x *= inv; r0.y *= inv; r0.z *= inv; r0.w *= inv;
            r1.x *= inv; r1.y *= inv; r1.z *= inv; r1.w *= inv;
        }

        // write X row s into SMEM: [h_hi | r_hi | h_lo | r_lo]
        float hvv[8] = {ha.x, ha.y, ha.z, ha.w, hb.x, hb.y, hb.z, hb.w};
        float rvv[8] = {r0.x, r0.y, r0.z, r0.w, r1.x, r1.y, r1.z, r1.w};
        float hlo[8], rlo[8];
#pragma unroll
        for (int i = 0; i < 8; ++i) {
            const __nv_bfloat16 hh = __float2bfloat16_rn(hvv[i]);
            const __nv_bfloat16 rh = __float2bfloat16_rn(rvv[i]);
            hlo[i] = hvv[i] - __bfloat162float(hh);
            rlo[i] = rvv[i] - __bfloat162float(rh);
        }
        __nv_bfloat16* xr = sX + (size_t)s * LDX + lane * 8;
        uint4 p;
        p.x = packbf2(hvv[0], hvv[1]); p.y = packbf2(hvv[2], hvv[3]);
        p.z = packbf2(hvv[4], hvv[5]); p.w = packbf2(hvv[6], hvv[7]);
        *(uint4*)(xr) = p;
        p.x = packbf2(rvv[0], rvv[1]); p.y = packbf2(rvv[2], rvv[3]);
        p.z = packbf2(rvv[4], rvv[5]); p.w = packbf2(rvv[6], rvv[7]);
        *(uint4*)(xr + 256) = p;
        p.x = packbf2(hlo[0], hlo[1]); p.y = packbf2(hlo[2], hlo[3]);
        p.z = packbf2(hlo[4], hlo[5]); p.w = packbf2(hlo[6], hlo[7]);
        *(uint4*)(xr + 512) = p;
        p.x = packbf2(rlo[0], rlo[1]); p.y = packbf2(rlo[2], rlo[3]);
        p.z = packbf2(rlo[4], rlo[5]); p.w = packbf2(rlo[6], rlo[7]);
        *(uint4*)(xr + 768) = p;
    }
    __syncthreads();   // X tile complete

    // ------------------ phase 2: GEMM + fused epilogue ---------------------
    const int gq = lane >> 2;
    const int t  = lane & 3;
    const int wm = warp >> 2;   // 0..1 (m16 tiles)
    const int wn = warp & 3;    // 0..3 (n16 tiles)
    const int lmrow = lane & 15;
    const int lmcol = (lane >> 4) * 8;

    float acc[2][4];

    for (int it = 0; it < NIT; ++it) {
        const int kt = it % NKT;
        const int n0 = (it / NKT) * 64;
        if (kt == 0) {
#pragma unroll
            for (int nt = 0; nt < 2; ++nt)
#pragma unroll
                for (int i = 0; i < 4; ++i) acc[nt][i] = 0.f;
        }

        cp_wait<NSTG - 2>();
        __syncthreads();   // tile it visible; slot (it+3)%4 reader-free

        const int p = it + NSTG - 1;
        if (p < NIT) {
            const int st = p % NSTG;
            const __nv_bfloat16* gb =
                g_Wc + (size_t)((p / NKT) * 64 + lrB) * K2 + (p % NKT) * BK;
            cp_async16(sB + st * BSTG + lrB * LDSK + cB0, gb + cB0);
            cp_async16(sB + st * BSTG + lrB * LDSK + cB1, gb + cB1);
        }
        cp_commit();

        const __nv_bfloat16* Bs = sB + (it % NSTG) * BSTG;
        const int aoff = a_koff(kt);

#pragma unroll
        for (int ks = 0; ks < 4; ++ks) {
            uint32_t af[4], bf[4];
            ldsm_x4(af, sX + (wm * 16 + lmrow) * LDX + aoff + ks * 16 + lmcol);
            ldsm_x4(bf, Bs + (wn * 16 + lmrow) * LDSK + ks * 16 + lmcol);
            mma16816(acc[0], af, bf[0], bf[2]);
            mma16816(acc[1], af, bf[1], bf[3]);
        }

        if (kt == NKT - 1) {
            // epilogue for n-chunk [n0, n0+64)
#pragma unroll
            for (int nt = 0; nt < 2; ++nt) {
                const int n = n0 + wn * 16 + nt * 8 + 2 * t;
                const float bi0 = Wg_b[n] + Ug_b[n] + b_g[n];
                const float bi1 = Wg_b[n + 1] + Ug_b[n + 1] + b_g[n + 1];
#pragma unroll
                for (int h2 = 0; h2 < 2; ++h2) {
                    const int lr  = wm * 16 + gq + 8 * h2;
                    const int row = samp0 + lr;
                    const bool has = lengths[row] > 0;
                    const __nv_bfloat162 rh =
                        *(const __nv_bfloat162*)(sX + (size_t)lr * LDX + 256 + n);
                    const __nv_bfloat162 rl =
                        *(const __nv_bfloat162*)(sX + (size_t)lr * LDX + 768 + n);
                    const float rx = __low2float(rh) + __low2float(rl);
                    const float ry = __high2float(rh) + __high2float(rl);
                    const size_t base = (size_t)row * D_SZ + n;
                    const float2 hv = *(const float2*)(h_tilde + base);
                    const float z0 = acc[nt][2 * h2 + 0] + bi0;
                    const float z1 = acc[nt][2 * h2 + 1] + bi1;
                    const float g0 = 1.f / (1.f + __expf(-z0));
                    const float g1 = 1.f / (1.f + __expf(-z1));
                    const float o0 = has ? (g0 * rx + (1.f - g0) * hv.x) : hv.x;
                    const float o1 = has ? (g1 * ry + (1.f - g1) * hv.y) : hv.y;
                    *(float2*)(out + base) = make_float2(o0, o1);
                }
            }
        }
    }
}

// ---------------------------------------------------------------------------
extern "C" void kernel_launch(void* const* d_in, const int* in_sizes, int n_in,
                              void* d_out, int out_size) {
    const float* h_tilde = (const float*)d_in[0];
    const float* mem     = (const float*)d_in[1];
    const int*   lengths = (const int*)d_in[2];
    const float* Wg_w    = (const float*)d_in[3];
    const float* Wg_b    = (const float*)d_in[4];
    const float* Ug_w    = (const float*)d_in[5];
    const float* Ug_b    = (const float*)d_in[6];
    const float* b_g     = (const float*)d_in[7];
    float* out = (float*)d_out;

    conv_w_kernel<<<768, 256>>>(Wg_w, Ug_w);

    const int smem_f = (SX_E + NSTG * BSTG) * (int)sizeof(__nv_bfloat16); // 102912
    cudaFuncSetAttribute(fused_kernel,
                         cudaFuncAttributeMaxDynamicSharedMemorySize, smem_f);
    fused_kernel<<<B_SZ / BM, 256, smem_f>>>(h_tilde, mem, lengths,
                                             Wg_b, Ug_b, b_g, out);
}

// round 11
// speedup vs baseline: 1.2551x; 1.2551x over previous
#include <cuda_runtime.h>
#include <cuda_bf16.h>
#include <cstdint>

#define B_SZ 8192
#define M_SZ 64
#define D_SZ 256
#define K1   1024   // Xc layout: [h_hi | r_hi | h_lo | r_lo]
#define K2   1536   // Wc layout: [W_hi | W_lo | W_hi]

// scratch (static device arrays — no allocation)
__device__ __align__(256) float          g_r[B_SZ * D_SZ];              // 8 MB
__device__ __align__(256) __nv_bfloat16  g_Xc[(size_t)B_SZ * K1];       // 16 MB
__device__ __align__(256) __nv_bfloat16  g_Wc[256 * K2];                // 768 KB

// ---------------------------------------------------------------------------
// helpers
// ---------------------------------------------------------------------------
__device__ __forceinline__ void cp_async16(void* smem_ptr, const void* gptr) {
    unsigned sa = (unsigned)__cvta_generic_to_shared(smem_ptr);
    asm volatile("cp.async.cg.shared.global [%0], [%1], 16;\n" :: "r"(sa), "l"(gptr));
}
__device__ __forceinline__ void cp_commit() {
    asm volatile("cp.async.commit_group;\n");
}
template<int N> __device__ __forceinline__ void cp_wait() {
    asm volatile("cp.async.wait_group %0;\n" :: "n"(N));
}
__device__ __forceinline__ void ldsm_x4(uint32_t r[4], const void* p) {
    unsigned a = (unsigned)__cvta_generic_to_shared(p);
    asm volatile("ldmatrix.sync.aligned.m8n8.x4.shared.b16 {%0,%1,%2,%3}, [%4];"
                 : "=r"(r[0]), "=r"(r[1]), "=r"(r[2]), "=r"(r[3]) : "r"(a));
}
__device__ __forceinline__ uint32_t packbf2(float x, float y) {
    __nv_bfloat162 t = __floats2bfloat162_rn(x, y);
    return *(uint32_t*)&t;
}

// ---------------------------------------------------------------------------
// Kernel A (proven round-8 version): warp-per-sample ragged attention.
// No barriers, no smem; register double-buffered row groups; online softmax.
// Blocks 0..1535 fold the W hi/lo bf16 conversion.
// ---------------------------------------------------------------------------
struct Grp { float4 v[4][2]; };

__global__ __launch_bounds__(128, 4)
void attn_r_kernel(const float* __restrict__ h_tilde,
                   const float* __restrict__ mem,
                   const int* __restrict__ lengths,
                   const float* __restrict__ Wg_w,
                   const float* __restrict__ Ug_w) {
    const int tid  = threadIdx.x;
    const int warp = tid >> 5;
    const int lane = tid & 31;
    const int blk  = blockIdx.x;

    // folded W conversion
    if (blk < 1536) {
        const int n  = blk / 6;
        const int j0 = (blk % 6) * 256 + tid * 2;
#pragma unroll
        for (int u = 0; u < 2; ++u) {
            const int j   = j0 + u;
            const int k   = j & 511;
            const int seg = j >> 9;
            const float w = (k < 256) ? Wg_w[n * 256 + k]
                                      : Ug_w[n * 256 + (k - 256)];
            const __nv_bfloat16 hi = __float2bfloat16_rn(w);
            g_Wc[n * K2 + j] = (seg == 1)
                ? __float2bfloat16_rn(w - __bfloat162float(hi)) : hi;
        }
    }

    const int b   = blk * 4 + warp;
    const int len = lengths[b];

    const float4* hp = (const float4*)(h_tilde + (size_t)b * D_SZ);
    const float4 ha = hp[lane * 2];
    const float4 hb = hp[lane * 2 + 1];

    float4 r0 = make_float4(0.f, 0.f, 0.f, 0.f);
    float4 r1 = make_float4(0.f, 0.f, 0.f, 0.f);

    if (len > 0) {
        const float4* base = (const float4*)(mem + (size_t)b * M_SZ * D_SZ);
        float Mrun = -3.0e38f, Srun = 0.f;

        Grp A, Bf;

        auto loadg = [&](Grp& R, int g) {
#pragma unroll
            for (int i = 0; i < 4; ++i) {
                const int m = g * 4 + i;
                R.v[i][0] = make_float4(0.f, 0.f, 0.f, 0.f);
                R.v[i][1] = make_float4(0.f, 0.f, 0.f, 0.f);
                if (m < len) {
                    const float4* rp = base + (size_t)m * 64 + lane * 2;
                    R.v[i][0] = rp[0];
                    R.v[i][1] = rp[1];
                }
            }
        };

        auto process = [&](const Grp& R, int g) {
            float sc[4];
#pragma unroll
            for (int i = 0; i < 4; ++i) {
                const float4 a = R.v[i][0];
                const float4 c = R.v[i][1];
                float acc = a.x * ha.x;
                acc = fmaf(a.y, ha.y, acc);
                acc = fmaf(a.z, ha.z, acc);
                acc = fmaf(a.w, ha.w, acc);
                acc = fmaf(c.x, hb.x, acc);
                acc = fmaf(c.y, hb.y, acc);
                acc = fmaf(c.z, hb.z, acc);
                acc = fmaf(c.w, hb.w, acc);
#pragma unroll
                for (int off = 16; off; off >>= 1)
                    acc += __shfl_xor_sync(0xffffffffu, acc, off);
                sc[i] = (g * 4 + i < len) ? acc : -1e9f;
            }
            const float cmax = fmaxf(fmaxf(sc[0], sc[1]), fmaxf(sc[2], sc[3]));
            const float nM   = fmaxf(Mrun, cmax);
            const float corr = __expf(Mrun - nM);
            const float e0 = __expf(sc[0] - nM);
            const float e1 = __expf(sc[1] - nM);
            const float e2 = __expf(sc[2] - nM);
            const float e3 = __expf(sc[3] - nM);
            Srun = Srun * corr + (e0 + e1) + (e2 + e3);
            Mrun = nM;
            r0.x = fmaf(e0, R.v[0][0].x, fmaf(e1, R.v[1][0].x, fmaf(e2, R.v[2][0].x, fmaf(e3, R.v[3][0].x, r0.x * corr))));
            r0.y = fmaf(e0, R.v[0][0].y, fmaf(e1, R.v[1][0].y, fmaf(e2, R.v[2][0].y, fmaf(e3, R.v[3][0].y, r0.y * corr))));
            r0.z = fmaf(e0, R.v[0][0].z, fmaf(e1, R.v[1][0].z, fmaf(e2, R.v[2][0].z, fmaf(e3, R.v[3][0].z, r0.z * corr))));
            r0.w = fmaf(e0, R.v[0][0].w, fmaf(e1, R.v[1][0].w, fmaf(e2, R.v[2][0].w, fmaf(e3, R.v[3][0].w, r0.w * corr))));
            r1.x = fmaf(e0, R.v[0][1].x, fmaf(e1, R.v[1][1].x, fmaf(e2, R.v[2][1].x, fmaf(e3, R.v[3][1].x, r1.x * corr))));
            r1.y = fmaf(e0, R.v[0][1].y, fmaf(e1, R.v[1][1].y, fmaf(e2, R.v[2][1].y, fmaf(e3, R.v[3][1].y, r1.y * corr))));
            r1.z = fmaf(e0, R.v[0][1].z, fmaf(e1, R.v[1][1].z, fmaf(e2, R.v[2][1].z, fmaf(e3, R.v[3][1].z, r1.z * corr))));
            r1.w = fmaf(e0, R.v[0][1].w, fmaf(e1, R.v[1][1].w, fmaf(e2, R.v[2][1].w, fmaf(e3, R.v[3][1].w, r1.w * corr))));
        };

        const int ng = (len + 3) >> 2;
        loadg(A, 0);
        int g = 0;
        while (true) {
            if (g + 1 < ng) loadg(Bf, g + 1);
            process(A, g);
            ++g;
            if (g >= ng) break;
            if (g + 1 < ng) loadg(A, g + 1);
            process(Bf, g);
            ++g;
            if (g >= ng) break;
        }

        const float inv = 1.f / Srun;
        r0.x *= inv; r0.y *= inv; r0.z *= inv; r0.w *= inv;
        r1.x *= inv; r1.y *= inv; r1.z *= inv; r1.w *= inv;
    }

    // store r
    float* gr = g_r + (size_t)b * D_SZ + lane * 8;
    *(float4*)gr       = r0;
    *(float4*)(gr + 4) = r1;

    // emit Xc row: [h_hi | r_hi | h_lo | r_lo], 8 values/lane per segment
    float hvv[8] = {ha.x, ha.y, ha.z, ha.w, hb.x, hb.y, hb.z, hb.w};
    float rvv[8] = {r0.x, r0.y, r0.z, r0.w, r1.x, r1.y, r1.z, r1.w};
    float hlo[8], rlo[8];
#pragma unroll
    for (int i = 0; i < 8; ++i) {
        const __nv_bfloat16 hh = __float2bfloat16_rn(hvv[i]);
        const __nv_bfloat16 rh = __float2bfloat16_rn(rvv[i]);
        hlo[i] = hvv[i] - __bfloat162float(hh);
        rlo[i] = rvv[i] - __bfloat162float(rh);
    }
    __nv_bfloat16* xr = g_Xc + (size_t)b * K1 + lane * 8;
    uint4 p;
    p.x = packbf2(hvv[0], hvv[1]); p.y = packbf2(hvv[2], hvv[3]);
    p.z = packbf2(hvv[4], hvv[5]); p.w = packbf2(hvv[6], hvv[7]);
    *(uint4*)(xr) = p;
    p.x = packbf2(rvv[0], rvv[1]); p.y = packbf2(rvv[2], rvv[3]);
    p.z = packbf2(rvv[4], rvv[5]); p.w = packbf2(rvv[6], rvv[7]);
    *(uint4*)(xr + 256) = p;
    p.x = packbf2(hlo[0], hlo[1]); p.y = packbf2(hlo[2], hlo[3]);
    p.z = packbf2(hlo[4], hlo[5]); p.w = packbf2(hlo[6], hlo[7]);
    *(uint4*)(xr + 512) = p;
    p.x = packbf2(rlo[0], rlo[1]); p.y = packbf2(rlo[2], rlo[3]);
    p.z = packbf2(rlo[4], rlo[5]); p.w = packbf2(rlo[6], rlo[7]);
    *(uint4*)(xr + 768) = p;
}

// ---------------------------------------------------------------------------
// Kernel B: bf16 tensor-core GEMM, virtual K=1536. BM=128, BN=128, BK=64.
// 512 threads (16 warps: 4 wm x 4 wn, warp tile 32x32). 3-stage cp.async,
// one barrier per k-tile, grid 64x2 = 128 CTAs, dyn smem 110.6 KB.
// ---------------------------------------------------------------------------
#define BM 128
#define BN 128
#define BK 64
#define LDSK 72                 // 64 bf16 + 16B pad -> ldmatrix conflict-free
#define STG (BM * LDSK)         // 9216 elems per operand per stage

__device__ __forceinline__ void mma16816(float c[4], const uint32_t a[4],
                                         const uint32_t b0, const uint32_t b1) {
    asm volatile(
        "mma.sync.aligned.m16n8k16.row.col.f32.bf16.bf16.f32 "
        "{%0,%1,%2,%3}, {%4,%5,%6,%7}, {%8,%9}, {%0,%1,%2,%3};\n"
        : "+f"(c[0]), "+f"(c[1]), "+f"(c[2]), "+f"(c[3])
        : "r"(a[0]), "r"(a[1]), "r"(a[2]), "r"(a[3]), "r"(b0), "r"(b1));
}

// virtual k-tile (BK=64, 24 tiles) -> A offset:
//  0..7: hi*Whi, 8..15: hi*Wlo, 16..23: lo*Whi
__device__ __forceinline__ int a_koff(int kt) {
    return (kt < 8) ? kt * BK : (kt < 16) ? (kt - 8) * BK
                                          : 512 + (kt - 16) * BK;
}

__global__ __launch_bounds__(512)
void gate_gemm_bf16(const float* __restrict__ h_tilde,
                    const float* __restrict__ Wg_b,
                    const float* __restrict__ Ug_b,
                    const float* __restrict__ b_g,
                    const int* __restrict__ lengths,
                    float* __restrict__ out) {
    extern __shared__ __align__(16) __nv_bfloat16 smem[];
    __nv_bfloat16* sA = smem;              // 3 * STG
    __nv_bfloat16* sB = smem + 3 * STG;    // 3 * STG

    const int tid  = threadIdx.x;
    const int warp = tid >> 5;
    const int lane = tid & 31;
    const int gq   = lane >> 2;
    const int t    = lane & 3;
    const int wm   = warp >> 2;       // 0..3
    const int wn   = warp & 3;        // 0..3
    const int bm0  = blockIdx.x * BM;
    const int bn0  = blockIdx.y * BN;

    float acc[2][4][4];               // [mt][j*2+nt][4]
#pragma unroll
    for (int mt = 0; mt < 2; ++mt)
#pragma unroll
        for (int q = 0; q < 4; ++q)
#pragma unroll
            for (int i = 0; i < 4; ++i) acc[mt][q][i] = 0.f;

    const __nv_bfloat16* gA = g_Xc + (size_t)bm0 * K1;
    const __nv_bfloat16* gB = g_Wc + (size_t)bn0 * K2;

    // loaders: 128 rows x 64 cols = 1024 16B-chunks per operand, 2/thread
    const int lr = tid >> 2;            // 0..127
    const int c0 = (tid & 3) * 8;       // {0,8,16,24}
    const int c1 = c0 + 32;             // {32,40,48,56}

    // prime k-tiles 0,1
#pragma unroll
    for (int p = 0; p < 2; ++p) {
        const int ao = a_koff(p), bo = p * BK;
        cp_async16(sA + p * STG + lr * LDSK + c0, gA + (size_t)lr * K1 + ao + c0);
        cp_async16(sA + p * STG + lr * LDSK + c1, gA + (size_t)lr * K1 + ao + c1);
        cp_async16(sB + p * STG + lr * LDSK + c0, gB + (size_t)lr * K2 + bo + c0);
        cp_async16(sB + p * STG + lr * LDSK + c1, gB + (size_t)lr * K2 + bo + c1);
        cp_commit();
    }

    const int lmrow = lane & 15;
    const int lmcol = (lane >> 4) * 8;

    const int NKT = K2 / BK;   // 24
    for (int kt = 0; kt < NKT; ++kt) {
        cp_wait<1>();
        __syncthreads();   // tile kt visible; slot (kt+2)%3 reader-free

        const int pc = kt + 2;
        if (pc < NKT) {
            const int st = pc % 3;
            const int ao = a_koff(pc), bo = pc * BK;
            cp_async16(sA + st * STG + lr * LDSK + c0, gA + (size_t)lr * K1 + ao + c0);
            cp_async16(sA + st * STG + lr * LDSK + c1, gA + (size_t)lr * K1 + ao + c1);
            cp_async16(sB + st * STG + lr * LDSK + c0, gB + (size_t)lr * K2 + bo + c0);
            cp_async16(sB + st * STG + lr * LDSK + c1, gB + (size_t)lr * K2 + bo + c1);
        }
        cp_commit();

        const __nv_bfloat16* A  = sA + (kt % 3) * STG;
        const __nv_bfloat16* Bs = sB + (kt % 3) * STG;

#pragma unroll
        for (int ks = 0; ks < 4; ++ks) {
            uint32_t af[2][4], bf[2][4];
#pragma unroll
            for (int mt = 0; mt < 2; ++mt)
                ldsm_x4(af[mt],
                        A + (wm * 32 + mt * 16 + lmrow) * LDSK + ks * 16 + lmcol);
#pragma unroll
            for (int j = 0; j < 2; ++j)
                ldsm_x4(bf[j],
                        Bs + (wn * 32 + j * 16 + lmrow) * LDSK + ks * 16 + lmcol);
#pragma unroll
            for (int mt = 0; mt < 2; ++mt) {
#pragma unroll
                for (int j = 0; j < 2; ++j) {
                    mma16816(acc[mt][2 * j],     af[mt], bf[j][0], bf[j][2]);
                    mma16816(acc[mt][2 * j + 1], af[mt], bf[j][1], bf[j][3]);
                }
            }
        }
    }

    // fused epilogue: bias + sigmoid + gate + has_mem mask
#pragma unroll
    for (int q = 0; q < 4; ++q) {
        const int n = bn0 + wn * 32 + (q >> 1) * 16 + (q & 1) * 8 + 2 * t;
        const float bi0 = Wg_b[n] + Ug_b[n] + b_g[n];
        const float bi1 = Wg_b[n + 1] + Ug_b[n + 1] + b_g[n + 1];
#pragma unroll
        for (int mt = 0; mt < 2; ++mt) {
#pragma unroll
            for (int h2 = 0; h2 < 2; ++h2) {
                const int row = bm0 + wm * 32 + mt * 16 + gq + 8 * h2;
                const bool has = lengths[row] > 0;
                const size_t base = (size_t)row * D_SZ + n;
                const float2 rv = *(const float2*)(g_r + base);
                const float2 hv = *(const float2*)(h_tilde + base);
                const float z0 = acc[mt][q][2 * h2 + 0] + bi0;
                const float z1 = acc[mt][q][2 * h2 + 1] + bi1;
                const float g0 = 1.f / (1.f + __expf(-z0));
                const float g1 = 1.f / (1.f + __expf(-z1));
                const float o0 = has ? (g0 * rv.x + (1.f - g0) * hv.x) : hv.x;
                const float o1 = has ? (g1 * rv.y + (1.f - g1) * hv.y) : hv.y;
                *(float2*)(out + base) = make_float2(o0, o1);
            }
        }
    }
}

// ---------------------------------------------------------------------------
extern "C" void kernel_launch(void* const* d_in, const int* in_sizes, int n_in,
                              void* d_out, int out_size) {
    const float* h_tilde = (const float*)d_in[0];
    const float* mem     = (const float*)d_in[1];
    const int*   lengths = (const int*)d_in[2];
    const float* Wg_w    = (const float*)d_in[3];
    const float* Wg_b    = (const float*)d_in[4];
    const float* Ug_w    = (const float*)d_in[5];
    const float* Ug_b    = (const float*)d_in[6];
    const float* b_g     = (const float*)d_in[7];
    float* out = (float*)d_out;

    attn_r_kernel<<<B_SZ / 4, 128>>>(h_tilde, mem, lengths, Wg_w, Ug_w);

    const int smem_b = 6 * STG * (int)sizeof(__nv_bfloat16);  // 110592
    cudaFuncSetAttribute(gate_gemm_bf16,
                         cudaFuncAttributeMaxDynamicSharedMemorySize, smem_b);
    dim3 gridB(B_SZ / BM, D_SZ / BN);   // 64 x 2
    gate_gemm_bf16<<<gridB, 512, smem_b>>>(h_tilde, Wg_b, Ug_b, b_g,
                                           lengths, out);
}

// round 15
// speedup vs baseline: 1.6370x; 1.3042x over previous
#include <cuda_runtime.h>
#include <cuda_fp16.h>
#include <cuda_bf16.h>
#include <cstdint>

#define B_SZ 8192
#define M_SZ 64
#define D_SZ 256
#define KX   512    // Xh layout: [h | r] fp16

// scratch (static device arrays — no allocation)
__device__ __align__(256) float  g_r[B_SZ * D_SZ];            // 8 MB
__device__ __align__(256) __half g_Xh[(size_t)B_SZ * KX];     // 8 MB
__device__ __align__(256) __half g_Wh[256 * KX];              // 256 KB

// ---------------------------------------------------------------------------
// helpers
// ---------------------------------------------------------------------------
__device__ __forceinline__ void cp_async16(void* smem_ptr, const void* gptr) {
    unsigned sa = (unsigned)__cvta_generic_to_shared(smem_ptr);
    asm volatile("cp.async.cg.shared.global [%0], [%1], 16;\n" :: "r"(sa), "l"(gptr));
}
__device__ __forceinline__ void cp_commit() {
    asm volatile("cp.async.commit_group;\n");
}
template<int N> __device__ __forceinline__ void cp_wait() {
    asm volatile("cp.async.wait_group %0;\n" :: "n"(N));
}
__device__ __forceinline__ void ldsm_x4(uint32_t r[4], const void* p) {
    unsigned a = (unsigned)__cvta_generic_to_shared(p);
    asm volatile("ldmatrix.sync.aligned.m8n8.x4.shared.b16 {%0,%1,%2,%3}, [%4];"
                 : "=r"(r[0]), "=r"(r[1]), "=r"(r[2]), "=r"(r[3]) : "r"(a));
}
__device__ __forceinline__ uint32_t packh2(float x, float y) {
    __half2 t = __floats2half2_rn(x, y);
    return *(uint32_t*)&t;
}

// ---------------------------------------------------------------------------
// Kernel A (proven round-8 structure): warp-per-sample ragged attention.
// No barriers, no smem; register double-buffered row groups; online softmax.
// Blocks 0..255 fold the fp16 W concat conversion (n = blk, 2 elems/thread).
// ---------------------------------------------------------------------------
struct Grp { float4 v[4][2]; };

__global__ __launch_bounds__(128, 4)
void attn_r_kernel(const float* __restrict__ h_tilde,
                   const float* __restrict__ mem,
                   const int* __restrict__ lengths,
                   const float* __restrict__ Wg_w,
                   const float* __restrict__ Ug_w) {
    const int tid  = threadIdx.x;
    const int warp = tid >> 5;
    const int lane = tid & 31;
    const int blk  = blockIdx.x;

    // folded W conversion: row n = [Wg_w[n,:] | Ug_w[n,:]] as fp16
    if (blk < 256) {
        const int n  = blk;
        const int j0 = tid * 2;
        const float w0 = (j0 < 256) ? Wg_w[n * 256 + j0]
                                    : Ug_w[n * 256 + (j0 - 256)];
        const float w1 = (j0 + 1 < 256) ? Wg_w[n * 256 + j0 + 1]
                                        : Ug_w[n * 256 + (j0 + 1 - 256)];
        *(uint32_t*)(g_Wh + (size_t)n * KX + j0) = packh2(w0, w1);
        const int j1 = j0 + 256;
        const float w2 = (j1 < 256) ? Wg_w[n * 256 + j1]
                                    : Ug_w[n * 256 + (j1 - 256)];
        const float w3 = (j1 + 1 < 256) ? Wg_w[n * 256 + j1 + 1]
                                        : Ug_w[n * 256 + (j1 + 1 - 256)];
        *(uint32_t*)(g_Wh + (size_t)n * KX + j1) = packh2(w2, w3);
    }

    const int b   = blk * 4 + warp;
    const int len = lengths[b];

    const float4* hp = (const float4*)(h_tilde + (size_t)b * D_SZ);
    const float4 ha = hp[lane * 2];
    const float4 hb = hp[lane * 2 + 1];

    float4 r0 = make_float4(0.f, 0.f, 0.f, 0.f);
    float4 r1 = make_float4(0.f, 0.f, 0.f, 0.f);

    if (len > 0) {
        const float4* base = (const float4*)(mem + (size_t)b * M_SZ * D_SZ);
        float Mrun = -3.0e38f, Srun = 0.f;

        Grp A, Bf;

        auto loadg = [&](Grp& R, int g) {
#pragma unroll
            for (int i = 0; i < 4; ++i) {
                const int m = g * 4 + i;
                R.v[i][0] = make_float4(0.f, 0.f, 0.f, 0.f);
                R.v[i][1] = make_float4(0.f, 0.f, 0.f, 0.f);
                if (m < len) {
                    const float4* rp = base + (size_t)m * 64 + lane * 2;
                    R.v[i][0] = rp[0];
                    R.v[i][1] = rp[1];
                }
            }
        };

        auto process = [&](const Grp& R, int g) {
            float sc[4];
#pragma unroll
            for (int i = 0; i < 4; ++i) {
                const float4 a = R.v[i][0];
                const float4 c = R.v[i][1];
                float acc = a.x * ha.x;
                acc = fmaf(a.y, ha.y, acc);
                acc = fmaf(a.z, ha.z, acc);
                acc = fmaf(a.w, ha.w, acc);
                acc = fmaf(c.x, hb.x, acc);
                acc = fmaf(c.y, hb.y, acc);
                acc = fmaf(c.z, hb.z, acc);
                acc = fmaf(c.w, hb.w, acc);
#pragma unroll
                for (int off = 16; off; off >>= 1)
                    acc += __shfl_xor_sync(0xffffffffu, acc, off);
                sc[i] = (g * 4 + i < len) ? acc : -1e9f;
            }
            const float cmax = fmaxf(fmaxf(sc[0], sc[1]), fmaxf(sc[2], sc[3]));
            const float nM   = fmaxf(Mrun, cmax);
            const float corr = __expf(Mrun - nM);
            const float e0 = __expf(sc[0] - nM);
            const float e1 = __expf(sc[1] - nM);
            const float e2 = __expf(sc[2] - nM);
            const float e3 = __expf(sc[3] - nM);
            Srun = Srun * corr + (e0 + e1) + (e2 + e3);
            Mrun = nM;
            r0.x = fmaf(e0, R.v[0][0].x, fmaf(e1, R.v[1][0].x, fmaf(e2, R.v[2][0].x, fmaf(e3, R.v[3][0].x, r0.x * corr))));
            r0.y = fmaf(e0, R.v[0][0].y, fmaf(e1, R.v[1][0].y, fmaf(e2, R.v[2][0].y, fmaf(e3, R.v[3][0].y, r0.y * corr))));
            r0.z = fmaf(e0, R.v[0][0].z, fmaf(e1, R.v[1][0].z, fmaf(e2, R.v[2][0].z, fmaf(e3, R.v[3][0].z, r0.z * corr))));
            r0.w = fmaf(e0, R.v[0][0].w, fmaf(e1, R.v[1][0].w, fmaf(e2, R.v[2][0].w, fmaf(e3, R.v[3][0].w, r0.w * corr))));
            r1.x = fmaf(e0, R.v[0][1].x, fmaf(e1, R.v[1][1].x, fmaf(e2, R.v[2][1].x, fmaf(e3, R.v[3][1].x, r1.x * corr))));
            r1.y = fmaf(e0, R.v[0][1].y, fmaf(e1, R.v[1][1].y, fmaf(e2, R.v[2][1].y, fmaf(e3, R.v[3][1].y, r1.y * corr))));
            r1.z = fmaf(e0, R.v[0][1].z, fmaf(e1, R.v[1][1].z, fmaf(e2, R.v[2][1].z, fmaf(e3, R.v[3][1].z, r1.z * corr))));
            r1.w = fmaf(e0, R.v[0][1].w, fmaf(e1, R.v[1][1].w, fmaf(e2, R.v[2][1].w, fmaf(e3, R.v[3][1].w, r1.w * corr))));
        };

        const int ng = (len + 3) >> 2;
        loadg(A, 0);
        int g = 0;
        while (true) {
            if (g + 1 < ng) loadg(Bf, g + 1);
            process(A, g);
            ++g;
            if (g >= ng) break;
            if (g + 1 < ng) loadg(A, g + 1);
            process(Bf, g);
            ++g;
            if (g >= ng) break;
        }

        const float inv = 1.f / Srun;
        r0.x *= inv; r0.y *= inv; r0.z *= inv; r0.w *= inv;
        r1.x *= inv; r1.y *= inv; r1.z *= inv; r1.w *= inv;
    }

    // store r (fp32, for the epilogue)
    float* gr = g_r + (size_t)b * D_SZ + lane * 8;
    *(float4*)gr       = r0;
    *(float4*)(gr + 4) = r1;

    // emit Xh row: [h | r] fp16, 8 values/lane per segment
    __half* xr = g_Xh + (size_t)b * KX + lane * 8;
    uint4 p;
    p.x = packh2(ha.x, ha.y); p.y = packh2(ha.z, ha.w);
    p.z = packh2(hb.x, hb.y); p.w = packh2(hb.z, hb.w);
    *(uint4*)(xr) = p;
    p.x = packh2(r0.x, r0.y); p.y = packh2(r0.z, r0.w);
    p.z = packh2(r1.x, r1.y); p.w = packh2(r1.z, r1.w);
    *(uint4*)(xr + 256) = p;
}

// ---------------------------------------------------------------------------
// Kernel B: fp16 tensor-core GEMM, K=512 single pass. BM=128, BN=128, BK=64.
// 512 threads (16 warps: 4 wm x 4 wn, warp tile 32x32). 3-stage cp.async,
// one barrier per k-tile, grid 64x2 = 128 CTAs, dyn smem 110.6 KB.
// ---------------------------------------------------------------------------
#define BM 128
#define BN 128
#define BK 64
#define LDSK 72                 // 64 f16 + 16B pad -> ldmatrix conflict-free
#define STG (BM * LDSK)         // 9216 elems per operand per stage

__device__ __forceinline__ void mma16816(float c[4], const uint32_t a[4],
                                         const uint32_t b0, const uint32_t b1) {
    asm volatile(
        "mma.sync.aligned.m16n8k16.row.col.f32.f16.f16.f32 "
        "{%0,%1,%2,%3}, {%4,%5,%6,%7}, {%8,%9}, {%0,%1,%2,%3};\n"
        : "+f"(c[0]), "+f"(c[1]), "+f"(c[2]), "+f"(c[3])
        : "r"(a[0]), "r"(a[1]), "r"(a[2]), "r"(a[3]), "r"(b0), "r"(b1));
}

__global__ __launch_bounds__(512)
void gate_gemm_f16(const float* __restrict__ h_tilde,
                   const float* __restrict__ Wg_b,
                   const float* __restrict__ Ug_b,
                   const float* __restrict__ b_g,
                   const int* __restrict__ lengths,
                   float* __restrict__ out) {
    extern __shared__ __align__(16) __half smem[];
    __half* sA = smem;              // 3 * STG
    __half* sB = smem + 3 * STG;    // 3 * STG

    const int tid  = threadIdx.x;
    const int warp = tid >> 5;
    const int lane = tid & 31;
    const int gq   = lane >> 2;
    const int t    = lane & 3;
    const int wm   = warp >> 2;       // 0..3
    const int wn   = warp & 3;        // 0..3
    const int bm0  = blockIdx.x * BM;
    const int bn0  = blockIdx.y * BN;

    float acc[2][4][4];               // [mt][j*2+nt][4]
#pragma unroll
    for (int mt = 0; mt < 2; ++mt)
#pragma unroll
        for (int q = 0; q < 4; ++q)
#pragma unroll
            for (int i = 0; i < 4; ++i) acc[mt][q][i] = 0.f;

    const __half* gA = g_Xh + (size_t)bm0 * KX;
    const __half* gB = g_Wh + (size_t)bn0 * KX;

    // loaders: 128 rows x 64 cols = 1024 16B-chunks per operand, 2/thread
    const int lr = tid >> 2;            // 0..127
    const int c0 = (tid & 3) * 8;       // {0,8,16,24}
    const int c1 = c0 + 32;             // {32,40,48,56}

    // prime k-tiles 0,1
#pragma unroll
    for (int p = 0; p < 2; ++p) {
        const int ko = p * BK;
        cp_async16(sA + p * STG + lr * LDSK + c0, gA + (size_t)lr * KX + ko + c0);
        cp_async16(sA + p * STG + lr * LDSK + c1, gA + (size_t)lr * KX + ko + c1);
        cp_async16(sB + p * STG + lr * LDSK + c0, gB + (size_t)lr * KX + ko + c0);
        cp_async16(sB + p * STG + lr * LDSK + c1, gB + (size_t)lr * KX + ko + c1);
        cp_commit();
    }

    const int lmrow = lane & 15;
    const int lmcol = (lane >> 4) * 8;

    const int NKT = KX / BK;   // 8
    for (int kt = 0; kt < NKT; ++kt) {
        cp_wait<1>();
        __syncthreads();   // tile kt visible; slot (kt+2)%3 reader-free

        const int pc = kt + 2;
        if (pc < NKT) {
            const int st = pc % 3;
            const int ko = pc * BK;
            cp_async16(sA + st * STG + lr * LDSK + c0, gA + (size_t)lr * KX + ko + c0);
            cp_async16(sA + st * STG + lr * LDSK + c1, gA + (size_t)lr * KX + ko + c1);
            cp_async16(sB + st * STG + lr * LDSK + c0, gB + (size_t)lr * KX + ko + c0);
            cp_async16(sB + st * STG + lr * LDSK + c1, gB + (size_t)lr * KX + ko + c1);
        }
        cp_commit();

        const __half* A  = sA + (kt % 3) * STG;
        const __half* Bs = sB + (kt % 3) * STG;

#pragma unroll
        for (int ks = 0; ks < 4; ++ks) {
            uint32_t af[2][4], bf[2][4];
#pragma unroll
            for (int mt = 0; mt < 2; ++mt)
                ldsm_x4(af[mt],
                        A + (wm * 32 + mt * 16 + lmrow) * LDSK + ks * 16 + lmcol);
#pragma unroll
            for (int j = 0; j < 2; ++j)
                ldsm_x4(bf[j],
                        Bs + (wn * 32 + j * 16 + lmrow) * LDSK + ks * 16 + lmcol);
#pragma unroll
            for (int mt = 0; mt < 2; ++mt) {
#pragma unroll
                for (int j = 0; j < 2; ++j) {
                    mma16816(acc[mt][2 * j],     af[mt], bf[j][0], bf[j][2]);
                    mma16816(acc[mt][2 * j + 1], af[mt], bf[j][1], bf[j][3]);
                }
            }
        }
    }

    // fused epilogue: bias + sigmoid + gate + has_mem mask
#pragma unroll
    for (int q = 0; q < 4; ++q) {
        const int n = bn0 + wn * 32 + (q >> 1) * 16 + (q & 1) * 8 + 2 * t;
        const float bi0 = Wg_b[n] + Ug_b[n] + b_g[n];
        const float bi1 = Wg_b[n + 1] + Ug_b[n + 1] + b_g[n + 1];
#pragma unroll
        for (int mt = 0; mt < 2; ++mt) {
#pragma unroll
            for (int h2 = 0; h2 < 2; ++h2) {
                const int row = bm0 + wm * 32 + mt * 16 + gq + 8 * h2;
                const bool has = lengths[row] > 0;
                const size_t base = (size_t)row * D_SZ + n;
                const float2 rv = *(const float2*)(g_r + base);
                const float2 hv = *(const float2*)(h_tilde + base);
                const float z0 = acc[mt][q][2 * h2 + 0] + bi0;
                const float z1 = acc[mt][q][2 * h2 + 1] + bi1;
                const float g0 = 1.f / (1.f + __expf(-z0));
                const float g1 = 1.f / (1.f + __expf(-z1));
                const float o0 = has ? (g0 * rv.x + (1.f - g0) * hv.x) : hv.x;
                const float o1 = has ? (g1 * rv.y + (1.f - g1) * hv.y) : hv.y;
                *(float2*)(out + base + 0) = make_float2(o0, o1);
            }
        }
    }
}

// ---------------------------------------------------------------------------
extern "C" void kernel_launch(void* const* d_in, const int* in_sizes, int n_in,
                              void* d_out, int out_size) {
    const float* h_tilde = (const float*)d_in[0];
    const float* mem     = (const float*)d_in[1];
    const int*   lengths = (const int*)d_in[2];
    const float* Wg_w    = (const float*)d_in[3];
    const float* Wg_b    = (const float*)d_in[4];
    const float* Ug_w    = (const float*)d_in[5];
    const float* Ug_b    = (const float*)d_in[6];
    const float* b_g     = (const float*)d_in[7];
    float* out = (float*)d_out;

    attn_r_kernel<<<B_SZ / 4, 128>>>(h_tilde, mem, lengths, Wg_w, Ug_w);

    const int smem_b = 6 * STG * (int)sizeof(__half);  // 110592
    cudaFuncSetAttribute(gate_gemm_f16,
                         cudaFuncAttributeMaxDynamicSharedMemorySize, smem_b);
    dim3 gridB(B_SZ / BM, D_SZ / BN);   // 64 x 2
    gate_gemm_f16<<<gridB, 512, smem_b>>>(h_tilde, Wg_b, Ug_b, b_g,
                                          lengths, out);
}